// round 1
// baseline (speedup 1.0000x reference)
#include <cuda_runtime.h>
#include <math.h>

// GridPostProcessor:
//   grid_logits: (R=50000, C=9, 28, 28) f32
//   det_bboxes : (R, 4) f32
//   out        : (R, 4) f32
//
// Per (r, c): max + argmax over 784 logits (sigmoid is monotonic, so argmax of
// logits == argmax of sigmoid; apply sigmoid only to the 9 winners).
// Epilogue: map argmax positions to absolute coords, score-weighted edge means.

#define HALF 28
#define HW   (HALF * HALF)     // 784
#define NV4  (HW / 4)          // 196 float4 per channel
#define CH   9

__global__ __launch_bounds__(288) void grid_post_kernel(
    const float* __restrict__ logits,
    const float* __restrict__ bboxes,
    float* __restrict__ out,
    int R)
{
    const int r    = blockIdx.x;
    const int warp = threadIdx.x >> 5;   // 0..8 -> channel
    const int lane = threadIdx.x & 31;

    __shared__ float s_max[CH];
    __shared__ int   s_idx[CH];

    if (r < R) {
        // ---- per-warp channel scan ----
        const float4* __restrict__ base =
            (const float4*)(logits + ((size_t)r * CH + warp) * HW);

        float best = -INFINITY;
        int   bidx = 0;

        // 196 float4 / 32 lanes: lanes 0..3 do 7 iters, rest 6.
        #pragma unroll
        for (int i = lane; i < NV4; i += 32) {
            float4 v = base[i];
            int j = i << 2;
            if (v.x > best) { best = v.x; bidx = j;     }
            if (v.y > best) { best = v.y; bidx = j + 1; }
            if (v.z > best) { best = v.z; bidx = j + 2; }
            if (v.w > best) { best = v.w; bidx = j + 3; }
        }

        // warp max+argmax reduce (first-occurrence tie-break)
        #pragma unroll
        for (int off = 16; off > 0; off >>= 1) {
            float ov = __shfl_down_sync(0xffffffffu, best, off);
            int   oi = __shfl_down_sync(0xffffffffu, bidx, off);
            if (ov > best || (ov == best && oi < bidx)) { best = ov; bidx = oi; }
        }
        if (lane == 0) { s_max[warp] = best; s_idx[warp] = bidx; }
    }
    __syncthreads();

    if (r < R && threadIdx.x == 0) {
        // sub-region offsets (GRID_SIZE=3, WHOLE_MAP=56, HALF=28):
        // off(0)=0, off(1)=14, off(2)=28
        const int sub_x[CH] = {0, 14, 28, 0, 14, 28, 0, 14, 28};
        const int sub_y[CH] = {0, 0, 0, 14, 14, 14, 28, 28, 28};

        const float bx1v = bboxes[r * 4 + 0];
        const float by1v = bboxes[r * 4 + 1];
        const float bx2v = bboxes[r * 4 + 2];
        const float by2v = bboxes[r * 4 + 3];
        const float width  = bx2v - bx1v;
        const float height = by2v - by1v;
        // MAPPING_RATIO = 1.0
        const float x1 = bx1v - 0.5f * width;
        const float y1 = by1v - 0.5f * height;

        float sc[CH], axs[CH], ays[CH];
        #pragma unroll
        for (int c = 0; c < CH; c++) {
            float v  = s_max[c];
            int   id = s_idx[c];
            sc[c] = 1.0f / (1.0f + expf(-v));
            int xs = (id % HALF) + sub_x[c];
            int ys = (id / HALF) + sub_y[c];
            // (xs+0.5)/(2*28) * (1+1) * width + x1 = (xs+0.5)*width/28 + x1
            axs[c] = ((float)xs + 0.5f) * (width  * (1.0f / 28.0f)) + x1;
            ays[c] = ((float)ys + 0.5f) * (height * (1.0f / 28.0f)) + y1;
        }

        // x1 edge: channels {0,1,2}; y1 edge: {0,3,6};
        // x2 edge: {6,7,8};          y2 edge: {2,5,8}
        float n_bx1 = axs[0]*sc[0] + axs[1]*sc[1] + axs[2]*sc[2];
        float d_bx1 = sc[0] + sc[1] + sc[2];
        float n_by1 = ays[0]*sc[0] + ays[3]*sc[3] + ays[6]*sc[6];
        float d_by1 = sc[0] + sc[3] + sc[6];
        float n_bx2 = axs[6]*sc[6] + axs[7]*sc[7] + axs[8]*sc[8];
        float d_bx2 = sc[6] + sc[7] + sc[8];
        float n_by2 = ays[2]*sc[2] + ays[5]*sc[5] + ays[8]*sc[8];
        float d_by2 = sc[2] + sc[5] + sc[8];

        out[r * 4 + 0] = n_bx1 / d_bx1;
        out[r * 4 + 1] = n_by1 / d_by1;
        out[r * 4 + 2] = n_bx2 / d_bx2;
        out[r * 4 + 3] = n_by2 / d_by2;
    }
}

extern "C" void kernel_launch(void* const* d_in, const int* in_sizes, int n_in,
                              void* d_out, int out_size) {
    const float* logits = (const float*)d_in[0];   // (R, 9, 28, 28)
    const float* bboxes = (const float*)d_in[1];   // (R, 4)
    float* out = (float*)d_out;                    // (R, 4)

    int R = in_sizes[0] / (CH * HW);               // 50000

    grid_post_kernel<<<R, 288>>>(logits, bboxes, out, R);
}

// round 2
// speedup vs baseline: 1.3085x; 1.3085x over previous
#include <cuda_runtime.h>
#include <math.h>

// GridPostProcessor (R=50000):
//   grid_logits: (R, 9, 28, 28) f32 -> per (r,c) max+argmax over 784
//   det_bboxes : (R, 4) f32
//   out        : (R, 4) f32
// Sigmoid is monotonic -> argmax on raw logits; sigmoid applied to the 9
// winners only, in the tiny epilogue kernel.

#define HALF 28
#define HW   (HALF * HALF)     // 784
#define NV4  (HW / 4)          // 196 float4 per channel
#define CH   9
#define RMAX 50000

// (maxval, idx-as-float) per (row, channel)
__device__ float2 g_mi[RMAX * CH];

// ---------------------------------------------------------------------------
// K1: one warp per (row, channel). 8 warps / 256-thread block.
// ---------------------------------------------------------------------------
__global__ __launch_bounds__(256) void k1_argmax(
    const float* __restrict__ logits, int total_wc /* R*9 */)
{
    const int w    = (blockIdx.x * blockDim.x + threadIdx.x) >> 5;
    const int lane = threadIdx.x & 31;
    if (w >= total_wc) return;

    const float4* __restrict__ base = (const float4*)(logits + (size_t)w * HW);

    // 196 vectors: lanes do vectors {lane + 32k, k=0..5}; lanes 0..3 also 192+lane.
    float4 v[7];
#pragma unroll
    for (int k = 0; k < 6; k++) v[k] = base[lane + 32 * k];
    v[6] = make_float4(-INFINITY, -INFINITY, -INFINITY, -INFINITY);
    if (lane < 4) v[6] = base[192 + lane];

    // 4 independent compare-select chains (one per component), length 7.
    // Within a chain idx is ascending, so strict '>' keeps first occurrence.
    float bx = v[0].x, by = v[0].y, bz = v[0].z, bw = v[0].w;
    int   ix = 0,      iy = 0,      iz = 0,      iw = 0;
#pragma unroll
    for (int k = 1; k < 7; k++) {
        if (v[k].x > bx) { bx = v[k].x; ix = k; }
        if (v[k].y > by) { by = v[k].y; iy = k; }
        if (v[k].z > bz) { bz = v[k].z; iz = k; }
        if (v[k].w > bw) { bw = v[k].w; iw = k; }
    }
    // element index for chain entry k: 4*vec + comp, vec = lane+32k (k<6) or 192+lane
    auto vec_of = [&](int k) { return (k < 6) ? (lane + 32 * k) : (192 + lane); };
    int ex = 4 * vec_of(ix) + 0;
    int ey = 4 * vec_of(iy) + 1;
    int ez = 4 * vec_of(iz) + 2;
    int ew = 4 * vec_of(iw) + 3;

    // merge chains with (val desc, idx asc) preference
    float best = bx; int bidx = ex;
    if (by > best || (by == best && ey < bidx)) { best = by; bidx = ey; }
    if (bz > best || (bz == best && ez < bidx)) { best = bz; bidx = ez; }
    if (bw > best || (bw == best && ew < bidx)) { best = bw; bidx = ew; }

    // warp reduce
#pragma unroll
    for (int off = 16; off > 0; off >>= 1) {
        float ov = __shfl_down_sync(0xffffffffu, best, off);
        int   oi = __shfl_down_sync(0xffffffffu, bidx, off);
        if (ov > best || (ov == best && oi < bidx)) { best = ov; bidx = oi; }
    }

    if (lane == 0) g_mi[w] = make_float2(best, __int_as_float(bidx));
}

// ---------------------------------------------------------------------------
// K2: epilogue, one thread per row.
// ---------------------------------------------------------------------------
__global__ __launch_bounds__(128) void k2_epilogue(
    const float* __restrict__ bboxes, float* __restrict__ out, int R)
{
    const int r = blockIdx.x * blockDim.x + threadIdx.x;
    if (r >= R) return;

    // sub-region offsets (GRID_SIZE=3, WHOLE_MAP=56): 0, 14, 28
    const int sub_x[CH] = {0, 14, 28, 0, 14, 28, 0, 14, 28};
    const int sub_y[CH] = {0, 0, 0, 14, 14, 14, 28, 28, 28};

    const float bx1v = bboxes[r * 4 + 0];
    const float by1v = bboxes[r * 4 + 1];
    const float bx2v = bboxes[r * 4 + 2];
    const float by2v = bboxes[r * 4 + 3];
    const float width  = bx2v - bx1v;
    const float height = by2v - by1v;
    const float x1 = bx1v - 0.5f * width;   // MAPPING_RATIO = 1
    const float y1 = by1v - 0.5f * height;
    const float wk = width  * (1.0f / 28.0f);
    const float hk = height * (1.0f / 28.0f);

    float sc[CH], axs[CH], ays[CH];
#pragma unroll
    for (int c = 0; c < CH; c++) {
        float2 mi = g_mi[r * CH + c];
        int id = __float_as_int(mi.y);
        sc[c] = 1.0f / (1.0f + __expf(-mi.x));
        int xs = (id % HALF) + sub_x[c];
        int ys = (id / HALF) + sub_y[c];
        axs[c] = ((float)xs + 0.5f) * wk + x1;
        ays[c] = ((float)ys + 0.5f) * hk + y1;
    }

    // x1 edge {0,1,2}; y1 edge {0,3,6}; x2 edge {6,7,8}; y2 edge {2,5,8}
    float n0 = axs[0]*sc[0] + axs[1]*sc[1] + axs[2]*sc[2];
    float d0 = sc[0] + sc[1] + sc[2];
    float n1 = ays[0]*sc[0] + ays[3]*sc[3] + ays[6]*sc[6];
    float d1 = sc[0] + sc[3] + sc[6];
    float n2 = axs[6]*sc[6] + axs[7]*sc[7] + axs[8]*sc[8];
    float d2 = sc[6] + sc[7] + sc[8];
    float n3 = ays[2]*sc[2] + ays[5]*sc[5] + ays[8]*sc[8];
    float d3 = sc[2] + sc[5] + sc[8];

    out[r * 4 + 0] = n0 / d0;
    out[r * 4 + 1] = n1 / d1;
    out[r * 4 + 2] = n2 / d2;
    out[r * 4 + 3] = n3 / d3;
}

extern "C" void kernel_launch(void* const* d_in, const int* in_sizes, int n_in,
                              void* d_out, int out_size) {
    const float* logits = (const float*)d_in[0];   // (R, 9, 28, 28)
    const float* bboxes = (const float*)d_in[1];   // (R, 4)
    float* out = (float*)d_out;                    // (R, 4)

    int R = in_sizes[0] / (CH * HW);               // 50000
    if (R > RMAX) R = RMAX;
    int total_wc = R * CH;                         // 450000 warps

    int blocks1 = (total_wc * 32 + 255) / 256;
    k1_argmax<<<blocks1, 256>>>(logits, total_wc);

    int blocks2 = (R + 127) / 128;
    k2_epilogue<<<blocks2, 128>>>(bboxes, out, R);
}

// round 3
// speedup vs baseline: 1.3323x; 1.0182x over previous
#include <cuda_runtime.h>
#include <math.h>

// GridPostProcessor (R=50000), fused single kernel:
//   grid_logits: (R, 9, 28, 28) f32 -> per (r,c) max+argmax over 784
//   det_bboxes : (R, 4) f32
//   out        : (R, 4) f32
// One block per row: 9 warps, warp c scans channel c (6 unconditional +
// 1 predicated float4 loads per lane, 4 independent compare chains),
// warp-shuffle reduce, epilogue parallelized across warp 0.

#define HALF 28
#define HW   (HALF * HALF)     // 784
#define CH   9

__global__ __launch_bounds__(288) void grid_post_fused(
    const float* __restrict__ logits,
    const float* __restrict__ bboxes,
    float* __restrict__ out,
    int R)
{
    const int r    = blockIdx.x;
    const int warp = threadIdx.x >> 5;   // channel
    const int lane = threadIdx.x & 31;

    __shared__ float  s_max[CH];
    __shared__ int    s_idx[CH];
    __shared__ float  s_sc[CH], s_ax[CH], s_ay[CH];

    // ---- per-warp channel scan (streaming loads, read-once) ----
    const float4* __restrict__ base =
        (const float4*)(logits + ((size_t)r * CH + warp) * HW);

    float4 v[7];
#pragma unroll
    for (int k = 0; k < 6; k++) v[k] = __ldcs(&base[lane + 32 * k]);
    v[6] = make_float4(-INFINITY, -INFINITY, -INFINITY, -INFINITY);
    if (lane < 4) v[6] = __ldcs(&base[192 + lane]);

    // 4 independent compare-select chains (idx ascending within a chain,
    // strict '>' keeps first occurrence).
    float bx = v[0].x, by = v[0].y, bz = v[0].z, bw = v[0].w;
    int   ix = 0,      iy = 0,      iz = 0,      iw = 0;
#pragma unroll
    for (int k = 1; k < 7; k++) {
        if (v[k].x > bx) { bx = v[k].x; ix = k; }
        if (v[k].y > by) { by = v[k].y; iy = k; }
        if (v[k].z > bz) { bz = v[k].z; iz = k; }
        if (v[k].w > bw) { bw = v[k].w; iw = k; }
    }
    auto vec_of = [&](int k) { return (k < 6) ? (lane + 32 * k) : (192 + lane); };
    int ex = 4 * vec_of(ix) + 0;
    int ey = 4 * vec_of(iy) + 1;
    int ez = 4 * vec_of(iz) + 2;
    int ew = 4 * vec_of(iw) + 3;

    float best = bx; int bidx = ex;
    if (by > best || (by == best && ey < bidx)) { best = by; bidx = ey; }
    if (bz > best || (bz == best && ez < bidx)) { best = bz; bidx = ez; }
    if (bw > best || (bw == best && ew < bidx)) { best = bw; bidx = ew; }

#pragma unroll
    for (int off = 16; off > 0; off >>= 1) {
        float ov = __shfl_down_sync(0xffffffffu, best, off);
        int   oi = __shfl_down_sync(0xffffffffu, bidx, off);
        if (ov > best || (ov == best && oi < bidx)) { best = ov; bidx = oi; }
    }
    if (lane == 0) { s_max[warp] = best; s_idx[warp] = bidx; }
    __syncthreads();

    // ---- epilogue: warp 0 only ----
    if (warp == 0) {
        // sub-region offsets (GRID_SIZE=3, WHOLE_MAP=56): 0, 14, 28
        const int sub_x[CH] = {0, 14, 28, 0, 14, 28, 0, 14, 28};
        const int sub_y[CH] = {0, 0, 0, 14, 14, 14, 28, 28, 28};

        const float bx1v = bboxes[r * 4 + 0];
        const float by1v = bboxes[r * 4 + 1];
        const float bx2v = bboxes[r * 4 + 2];
        const float by2v = bboxes[r * 4 + 3];
        const float width  = bx2v - bx1v;
        const float height = by2v - by1v;
        const float x1 = bx1v - 0.5f * width;    // MAPPING_RATIO = 1
        const float y1 = by1v - 0.5f * height;
        const float wk = width  * (1.0f / 28.0f);
        const float hk = height * (1.0f / 28.0f);

        if (lane < CH) {
            float mv = s_max[lane];
            int   id = s_idx[lane];
            s_sc[lane] = 1.0f / (1.0f + __expf(-mv));
            int xs = (id % HALF) + sub_x[lane];
            int ys = (id / HALF) + sub_y[lane];
            s_ax[lane] = ((float)xs + 0.5f) * wk + x1;
            s_ay[lane] = ((float)ys + 0.5f) * hk + y1;
        }
        __syncwarp();

        if (lane < 4) {
            // edge channel triplets:
            //   out0 (bx1): x over {0,1,2}; out1 (by1): y over {0,3,6}
            //   out2 (bx2): x over {6,7,8}; out3 (by2): y over {2,5,8}
            const int e0[4] = {0, 0, 6, 2};
            const int e1[4] = {1, 3, 7, 5};
            const int e2[4] = {2, 6, 8, 8};
            int c0 = e0[lane], c1 = e1[lane], c2 = e2[lane];
            const float* coord = (lane & 1) ? s_ay : s_ax;
            float num = coord[c0] * s_sc[c0] + coord[c1] * s_sc[c1] + coord[c2] * s_sc[c2];
            float den = s_sc[c0] + s_sc[c1] + s_sc[c2];
            out[r * 4 + lane] = num / den;
        }
    }
}

extern "C" void kernel_launch(void* const* d_in, const int* in_sizes, int n_in,
                              void* d_out, int out_size) {
    const float* logits = (const float*)d_in[0];   // (R, 9, 28, 28)
    const float* bboxes = (const float*)d_in[1];   // (R, 4)
    float* out = (float*)d_out;                    // (R, 4)

    int R = in_sizes[0] / (CH * HW);               // 50000

    grid_post_fused<<<R, 288>>>(logits, bboxes, out, R);
}